// round 5
// baseline (speedup 1.0000x reference)
#include <cuda_runtime.h>
#include <cstdint>

#define NBLK 148
#define NTHR 512

// ---------------- static device scratch ----------------
__device__ __align__(16) float g_P[5767168];
__device__ __align__(16) float g_oatt[64 * 512];
__device__ __align__(16) float g_res1[64 * 512];
__device__ __align__(16) float g_part[64 * 8 * 512];
__device__ __align__(16) float g_wpart[512];
__device__ float g_dummy[8];
// [0]=attention steal, [1]=prefetch steal, flags at 64 + bid*32 (one 128B line per CTA)
__device__ unsigned g_sync[64 + 148 * 32];

// partial-region offsets (floats)
#define OFF_P1 0        // pre1:  ns=3,  ldp=512
#define OFF_P2 98304    // pre2:  ns=8,  ldp=256
#define OFF_A  229376   // gruA:  ns=12, ldp=1536
#define OFF_W  1409024  // wdec:  ns=8,  ldp=512
#define OFF_G  1671168  // wsc|g1:ns=18, ldp=2048
#define OFF_2  4030464  // g2:    ns=16, ldp=1536
#define OFF_O  5603328  // wout:  ns=16, ldp=160

__device__ __forceinline__ float tanh_fast(float x) {
    float y; asm("tanh.approx.f32 %0, %1;" : "=f"(y) : "f"(x)); return y;
}
__device__ __forceinline__ float gru_out(float gr, float gz, float gn,
                                         float br, float bz, float bn) {
    float r  = 1.f / (1.f + __expf(-(gr + br)));
    float z  = 1.f / (1.f + __expf(-(gz + bz)));
    float nn = tanhf(gn + r * bn);
    return (1.f - z) * nn;
}
__device__ __forceinline__ void add4(float4& a, const float4 b) {
    a.x += b.x; a.y += b.y; a.z += b.z; a.w += b.w;
}
__device__ __forceinline__ void bar_half(int half) {
    asm volatile("bar.sync %0, 256;" :: "r"(half + 1) : "memory");
}

// flag-array grid barrier: per-CTA release-store, distributed acquire-poll.
__device__ __forceinline__ void gbar(unsigned ep) {
    __syncthreads();
    if (threadIdx.x == 0) {
        asm volatile("st.release.gpu.global.u32 [%0], %1;"
                     :: "l"(g_sync + 64 + blockIdx.x * 32), "r"(ep) : "memory");
    }
    if (threadIdx.x < 148) {
        const unsigned* p = g_sync + 64 + threadIdx.x * 32;
        unsigned v;
        do {
            asm volatile("ld.acquire.gpu.global.u32 %0, [%1];"
                         : "=r"(v) : "l"(p) : "memory");
        } while (v < ep);
    }
    __syncthreads();
}

// ---------------- L2 prefetch of enc/encW live chunks (16 rows = 32 KB each) ----------------
// id space [0,8192): item = id>>4 (attention item order), tensor = (id>>3)&1, sub = id&7.
__device__ float prefetch_batch(const float* __restrict__ enc, const float* __restrict__ encW,
                                const int* __restrict__ len, int nbatch,
                                float* __restrict__ smh, int half, int htid)
{
    int* ip = (int*)smh;
    float s = 0.f;
    for (int b = 0; b < nbatch; b++) {
        if (htid == 0) *ip = (int)atomicAdd(&g_sync[1], 4u);
        bar_half(half);
        int base = *ip;
        bar_half(half);
        if (base >= 8192) return s;
        for (int q = 0; q < 4; q++) {
            int idx = base + q;
            if (idx >= 8192) break;
            int item = idx >> 4, tensor = (idx >> 3) & 1, sub = idx & 7;
            int n = item >> 3, t0 = ((item & 7) << 7) + (sub << 4);
            int L = len[n];
            if (t0 >= L) continue;
            int rows = min(16, L - t0);
            const float4* p = reinterpret_cast<const float4*>(
                (tensor ? enc : encW) + ((size_t)(n * 1024 + t0)) * 512);
            for (int i = htid; i < rows * 128; i += 256) s += p[i].x;
        }
    }
    return s;
}

// ---------------- X functors ----------------
struct XDirect {
    const float* X; int ldx;
    __device__ __forceinline__ float4 load4(int n, int k) const {
        return *reinterpret_cast<const float4*>(X + (size_t)n * ldx + k);
    }
    __device__ __forceinline__ float load1(int n, int k) const {
        return X[(size_t)n * ldx + k];
    }
};
struct XPre1Red {
    const float* P1; const float* pb1;
    __device__ __forceinline__ float4 load4(int n, int k) const {
        float4 s = *reinterpret_cast<const float4*>(pb1 + k);
#pragma unroll
        for (int sp = 0; sp < 3; sp++)
            add4(s, *reinterpret_cast<const float4*>(P1 + sp * 32768 + n * 512 + k));
        s.x = fmaxf(s.x, 0.f); s.y = fmaxf(s.y, 0.f);
        s.z = fmaxf(s.z, 0.f); s.w = fmaxf(s.w, 0.f);
        return s;
    }
    __device__ __forceinline__ float load1(int n, int k) const {
        float s = pb1[k];
        for (int sp = 0; sp < 3; sp++) s += P1[sp * 32768 + n * 512 + k];
        return fmaxf(s, 0.f);
    }
};
struct XPre2Red {
    const float* P2; const float* pb2; const float* sv;
    __device__ __forceinline__ float4 load4(int n, int k) const {
        if (k < 256) {
            float4 s = *reinterpret_cast<const float4*>(pb2 + k);
#pragma unroll
            for (int sp = 0; sp < 8; sp++)
                add4(s, *reinterpret_cast<const float4*>(P2 + sp * 16384 + n * 256 + k));
            s.x = fmaxf(s.x, 0.f); s.y = fmaxf(s.y, 0.f);
            s.z = fmaxf(s.z, 0.f); s.w = fmaxf(s.w, 0.f);
            return s;
        }
        return *reinterpret_cast<const float4*>(sv + n * 128 + (k - 256));
    }
    __device__ __forceinline__ float load1(int n, int k) const {
        if (k < 256) {
            float s = pb2[k];
            for (int sp = 0; sp < 8; sp++) s += P2[sp * 16384 + n * 256 + k];
            return fmaxf(s, 0.f);
        }
        return sv[n * 128 + (k - 256)];
    }
};
struct XGruARed {
    const float* P; const float* bih; const float* bhh;
    __device__ __forceinline__ float4 load4(int n, int k) const {
        const float* b = P + (size_t)n * 1536 + k;
        float4 r = *reinterpret_cast<const float4*>(bih + k);
        float4 z = *reinterpret_cast<const float4*>(bih + 512 + k);
        float4 m = *reinterpret_cast<const float4*>(bih + 1024 + k);
#pragma unroll
        for (int sp = 0; sp < 12; sp++) {
            const float* q = b + (size_t)sp * 98304;
            add4(r, *reinterpret_cast<const float4*>(q));
            add4(z, *reinterpret_cast<const float4*>(q + 512));
            add4(m, *reinterpret_cast<const float4*>(q + 1024));
        }
        float4 br = *reinterpret_cast<const float4*>(bhh + k);
        float4 bz = *reinterpret_cast<const float4*>(bhh + 512 + k);
        float4 bn = *reinterpret_cast<const float4*>(bhh + 1024 + k);
        float4 o;
        o.x = gru_out(r.x, z.x, m.x, br.x, bz.x, bn.x);
        o.y = gru_out(r.y, z.y, m.y, br.y, bz.y, bn.y);
        o.z = gru_out(r.z, z.z, m.z, br.z, bz.z, bn.z);
        o.w = gru_out(r.w, z.w, m.w, br.w, bz.w, bn.w);
        return o;
    }
    __device__ __forceinline__ float load1(int n, int k) const {
        float gr = bih[k], gz = bih[512 + k], gn = bih[1024 + k];
        for (int sp = 0; sp < 12; sp++) {
            const float* q = P + (size_t)sp * 98304 + (size_t)n * 1536 + k;
            gr += q[0]; gz += q[512]; gn += q[1024];
        }
        return gru_out(gr, gz, gn, bhh[k], bhh[512 + k], bhh[1024 + k]);
    }
};
struct XOdecRed {
    const float* part; const float* wpart; const float* oatt; const float* sv;
    __device__ __forceinline__ float4 load4(int n, int k) const {
        if (k < 512) {
            float4 s = make_float4(0.f, 0.f, 0.f, 0.f);
            float w = 0.f;
#pragma unroll
            for (int sp = 0; sp < 8; sp++) {
                add4(s, *reinterpret_cast<const float4*>(part + (size_t)(n * 8 + sp) * 512 + k));
                w += wpart[n * 8 + sp];
            }
            float inv = 1.f / fmaxf(w, 1e-12f);
            s.x *= inv; s.y *= inv; s.z *= inv; s.w *= inv;
            return s;
        }
        if (k < 1024) return *reinterpret_cast<const float4*>(oatt + n * 512 + (k - 512));
        return *reinterpret_cast<const float4*>(sv + n * 128 + (k - 1024));
    }
    __device__ __forceinline__ float load1(int n, int k) const {
        if (k < 512) {
            float s = 0.f, w = 0.f;
            for (int sp = 0; sp < 8; sp++) {
                s += part[(size_t)(n * 8 + sp) * 512 + k];
                w += wpart[n * 8 + sp];
            }
            return s / fmaxf(w, 1e-12f);
        }
        if (k < 1024) return oatt[n * 512 + (k - 512)];
        return sv[n * 128 + (k - 1024)];
    }
};
struct XGru2Red {
    const float* P; const float* bih; const float* bhh; const float* res1;
    __device__ __forceinline__ float4 load4(int n, int k) const {
        const float* b = P + (size_t)n * 1536 + k;
        float4 r = *reinterpret_cast<const float4*>(bih + k);
        float4 z = *reinterpret_cast<const float4*>(bih + 512 + k);
        float4 m = *reinterpret_cast<const float4*>(bih + 1024 + k);
#pragma unroll
        for (int sp = 0; sp < 16; sp++) {
            const float* q = b + (size_t)sp * 98304;
            add4(r, *reinterpret_cast<const float4*>(q));
            add4(z, *reinterpret_cast<const float4*>(q + 512));
            add4(m, *reinterpret_cast<const float4*>(q + 1024));
        }
        float4 br = *reinterpret_cast<const float4*>(bhh + k);
        float4 bz = *reinterpret_cast<const float4*>(bhh + 512 + k);
        float4 bn = *reinterpret_cast<const float4*>(bhh + 1024 + k);
        float4 rv = *reinterpret_cast<const float4*>(res1 + n * 512 + k);
        float4 o;
        o.x = gru_out(r.x, z.x, m.x, br.x, bz.x, bn.x) + rv.x;
        o.y = gru_out(r.y, z.y, m.y, br.y, bz.y, bn.y) + rv.y;
        o.z = gru_out(r.z, z.z, m.z, br.z, bz.z, bn.z) + rv.z;
        o.w = gru_out(r.w, z.w, m.w, br.w, bz.w, bn.w) + rv.w;
        return o;
    }
    __device__ __forceinline__ float load1(int n, int k) const {
        float gr = bih[k], gz = bih[512 + k], gn = bih[1024 + k];
        for (int sp = 0; sp < 16; sp++) {
            const float* q = P + (size_t)sp * 98304 + (size_t)n * 1536 + k;
            gr += q[0]; gz += q[512]; gn += q[1024];
        }
        return gru_out(gr, gz, gn, bhh[k], bhh[512 + k], bhh[1024 + k]) + res1[n * 512 + k];
    }
};

// ---------------- dual-worker k-split GEMM stage ----------------
template <int KC, class XF>
__device__ __forceinline__ void gemm_stage(
    const XF xf,
    const float* __restrict__ W1, int m1, const float* __restrict__ W2, int ldw,
    int kjump_at, int kjump_ofs,
    int M, int K, int jt_n, int ks_n,
    float* __restrict__ P, int ldp, float* __restrict__ smh, int half, int htid)
{
    constexpr int K4 = KC / 4;
    constexpr int SH = (KC == 64) ? 4 : 3;
    float* xs = smh;            // [KC][68]
    float* ws = smh + KC * 68;  // [KC][132]
    const int items = jt_n * ks_n;

    for (int it = blockIdx.x * 2 + half; it < items; it += 2 * NBLK) {
        const int ksp = it / jt_n;
        const int jt  = it - ksp * jt_n;
        const int j0  = jt << 7;
        const int k0  = ksp * KC;
        for (int idx = htid; idx < K4 * 64; idx += 256) {
            int k4 = idx & (K4 - 1), n = idx >> SH;
            int kk = k0 + (k4 << 2);
            float4 v = make_float4(0.f, 0.f, 0.f, 0.f);
            if (kk + 3 < K) v = xf.load4(n, kk);
            else {
                if (kk + 0 < K) v.x = xf.load1(n, kk + 0);
                if (kk + 1 < K) v.y = xf.load1(n, kk + 1);
                if (kk + 2 < K) v.z = xf.load1(n, kk + 2);
                if (kk + 3 < K) v.w = xf.load1(n, kk + 3);
            }
            float* d = xs + (k4 << 2) * 68 + n;
            d[0] = v.x; d[68] = v.y; d[136] = v.z; d[204] = v.w;
        }
        const int wofs = k0 + (k0 >= kjump_at ? kjump_ofs : 0);
        for (int idx = htid; idx < K4 * 128; idx += 256) {
            int k4 = idx & (K4 - 1), j = idx >> SH;
            int jr = j0 + j;
            float4 v = make_float4(0.f, 0.f, 0.f, 0.f);
            if (jr < M) {
                const float* Wr = (jr < m1) ? (W1 + (size_t)jr * ldw)
                                            : (W2 + (size_t)(jr - m1) * ldw);
                int kk = k0 + (k4 << 2);
                if (kk + 3 < K) v = *reinterpret_cast<const float4*>(Wr + wofs + (k4 << 2));
                else {
                    if (kk + 0 < K) v.x = Wr[wofs + (k4 << 2) + 0];
                    if (kk + 1 < K) v.y = Wr[wofs + (k4 << 2) + 1];
                    if (kk + 2 < K) v.z = Wr[wofs + (k4 << 2) + 2];
                    if (kk + 3 < K) v.w = Wr[wofs + (k4 << 2) + 3];
                }
            }
            float* d = ws + (k4 << 2) * 132 + j;
            d[0] = v.x; d[132] = v.y; d[264] = v.z; d[396] = v.w;
        }
        bar_half(half);

        const int tj = htid & 31, tn = htid >> 5;
        float acc[4][8];
#pragma unroll
        for (int a = 0; a < 4; a++)
#pragma unroll
            for (int b = 0; b < 8; b++) acc[a][b] = 0.f;

#pragma unroll 8
        for (int k = 0; k < KC; k++) {
            float4 wv = *reinterpret_cast<const float4*>(ws + k * 132 + tj * 4);
            float4 xa = *reinterpret_cast<const float4*>(xs + k * 68 + tn * 8);
            float4 xb = *reinterpret_cast<const float4*>(xs + k * 68 + tn * 8 + 4);
            float xv[8] = {xa.x, xa.y, xa.z, xa.w, xb.x, xb.y, xb.z, xb.w};
            float wr[4] = {wv.x, wv.y, wv.z, wv.w};
#pragma unroll
            for (int jj = 0; jj < 4; jj++)
#pragma unroll
                for (int i = 0; i < 8; i++) acc[jj][i] += wr[jj] * xv[i];
        }

        if (j0 + tj * 4 < M) {
            float* base = P + (size_t)ksp * (64 * ldp) + j0 + tj * 4;
#pragma unroll
            for (int i = 0; i < 8; i++) {
                int n = tn * 8 + i;
                *reinterpret_cast<float4*>(base + (size_t)n * ldp) =
                    make_float4(acc[0][i], acc[1][i], acc[2][i], acc[3][i]);
            }
        }
        bar_half(half);
    }
}

// ---------------- attention: phase A (scores) + phase B (column stream) ----------------
__device__ void attention_phase(const float* __restrict__ encW, const float* __restrict__ enc,
                                const float* __restrict__ wattn, const float* __restrict__ battn,
                                const float* __restrict__ bdec, const int* __restrict__ len,
                                float* __restrict__ smh, int half, int htid)
{
    float* wv_s = smh;           // 512
    float* aw_s = smh + 512;     // 512
    float* we_s = smh + 1024;    // 128
    float* wred = smh + 1152;    // 8
    int*   ip   = (int*)(smh + 1160);
    float* cacc = smh + 1168;    // 256 float4
    const float* PW = g_P + OFF_W;
    const int lane = htid & 31, warp = htid >> 5;
    const float bat = battn[0];

    for (int c = htid; c < 512; c += 256) wv_s[c] = wattn[c];

    for (;;) {
        if (htid == 0) *ip = (int)atomicAdd(&g_sync[0], 1u);
        bar_half(half);
        const int item = *ip;
        bar_half(half);
        if (item >= 512) break;
        const int n = item >> 3, t0 = (item & 7) << 7;
        const int tc = min(128, len[n] - t0);
        if (tc <= 0) {
            for (int c = htid; c < 512; c += 256) g_part[(size_t)item * 512 + c] = 0.f;
            if (htid == 0) g_wpart[item] = 0.f;
            continue;
        }
        // build attW[n] from wdec partials (+ bdec)
        for (int c4 = htid; c4 < 128; c4 += 256) {
            int c = c4 << 2;
            float4 s = *reinterpret_cast<const float4*>(bdec + c);
#pragma unroll
            for (int sp = 0; sp < 8; sp++)
                add4(s, *reinterpret_cast<const float4*>(PW + sp * 32768 + n * 512 + c));
            *reinterpret_cast<float4*>(aw_s + c) = s;
        }
        bar_half(half);

        // phase A: scores -> we_s (streams encW)
        float wsum = 0.f;
        const size_t rb = (size_t)(n * 1024 + t0) * 512;
        for (int tt = warp * 2; tt < tc; tt += 16) {
            const bool ok1 = (tt + 1 < tc);
            const float* r0 = encW + rb + (size_t)tt * 512;
            float4 a0[4], a1[4];
#pragma unroll
            for (int q = 0; q < 4; q++) {
                int c = lane * 4 + q * 128;
                a0[q] = *reinterpret_cast<const float4*>(r0 + c);
                a1[q] = ok1 ? *reinterpret_cast<const float4*>(r0 + 512 + c)
                            : make_float4(0.f, 0.f, 0.f, 0.f);
            }
            float s0 = 0.f, s1 = 0.f;
#pragma unroll
            for (int q = 0; q < 4; q++) {
                int c = lane * 4 + q * 128;
                float4 aw = *reinterpret_cast<const float4*>(aw_s + c);
                float4 wv = *reinterpret_cast<const float4*>(wv_s + c);
                s0 += tanh_fast(a0[q].x + aw.x) * wv.x + tanh_fast(a0[q].y + aw.y) * wv.y
                    + tanh_fast(a0[q].z + aw.z) * wv.z + tanh_fast(a0[q].w + aw.w) * wv.w;
                s1 += tanh_fast(a1[q].x + aw.x) * wv.x + tanh_fast(a1[q].y + aw.y) * wv.y
                    + tanh_fast(a1[q].z + aw.z) * wv.z + tanh_fast(a1[q].w + aw.w) * wv.w;
            }
#pragma unroll
            for (int o = 16; o > 0; o >>= 1) {
                s0 += __shfl_xor_sync(0xffffffffu, s0, o);
                s1 += __shfl_xor_sync(0xffffffffu, s1, o);
            }
            if (lane == 0) {
                float w0 = __expf(s0 + bat);
                float w1 = ok1 ? __expf(s1 + bat) : 0.f;
                we_s[tt] = w0;
                if (ok1) we_s[tt + 1] = w1;
                wsum += w0 + w1;
            }
        }
        if (lane == 0) wred[warp] = wsum;
        bar_half(half);

        // phase B: weighted column sums (streams enc; no shuffles, deep MLP)
        {
            const int col = (htid & 127) << 2;
            const int rh = htid >> 7;
            const float* base = enc + rb + col;
            float4 acc = make_float4(0.f, 0.f, 0.f, 0.f);
            int r = rh;
            for (; r + 14 < tc; r += 16) {
                float w0 = we_s[r],      w1 = we_s[r + 2],  w2 = we_s[r + 4],  w3 = we_s[r + 6];
                float w4 = we_s[r + 8],  w5 = we_s[r + 10], w6 = we_s[r + 12], w7 = we_s[r + 14];
                float4 v0 = *reinterpret_cast<const float4*>(base + (size_t)(r +  0) * 512);
                float4 v1 = *reinterpret_cast<const float4*>(base + (size_t)(r +  2) * 512);
                float4 v2 = *reinterpret_cast<const float4*>(base + (size_t)(r +  4) * 512);
                float4 v3 = *reinterpret_cast<const float4*>(base + (size_t)(r +  6) * 512);
                float4 v4 = *reinterpret_cast<const float4*>(base + (size_t)(r +  8) * 512);
                float4 v5 = *reinterpret_cast<const float4*>(base + (size_t)(r + 10) * 512);
                float4 v6 = *reinterpret_cast<const float4*>(base + (size_t)(r + 12) * 512);
                float4 v7 = *reinterpret_cast<const float4*>(base + (size_t)(r + 14) * 512);
                acc.x += w0*v0.x + w1*v1.x + w2*v2.x + w3*v3.x + w4*v4.x + w5*v5.x + w6*v6.x + w7*v7.x;
                acc.y += w0*v0.y + w1*v1.y + w2*v2.y + w3*v3.y + w4*v4.y + w5*v5.y + w6*v6.y + w7*v7.y;
                acc.z += w0*v0.z + w1*v1.z + w2*v2.z + w3*v3.z + w4*v4.z + w5*v5.z + w6*v6.z + w7*v7.z;
                acc.w += w0*v0.w + w1*v1.w + w2*v2.w + w3*v3.w + w4*v4.w + w5*v5.w + w6*v6.w + w7*v7.w;
            }
            for (; r < tc; r += 2) {
                float w = we_s[r];
                float4 v = *reinterpret_cast<const float4*>(base + (size_t)r * 512);
                acc.x += w * v.x; acc.y += w * v.y; acc.z += w * v.z; acc.w += w * v.w;
            }
            *reinterpret_cast<float4*>(cacc + htid * 4) = acc;
        }
        bar_half(half);
        if (htid < 128) {
            float4 x = *reinterpret_cast<const float4*>(cacc + htid * 4);
            float4 y = *reinterpret_cast<const float4*>(cacc + (htid + 128) * 4);
            add4(x, y);
            *reinterpret_cast<float4*>(g_part + (size_t)item * 512 + htid * 4) = x;
        }
        if (htid == 0) {
            float s = 0.f;
#pragma unroll
            for (int w = 0; w < 8; w++) s += wred[w];
            g_wpart[item] = s;
        }
        bar_half(half);
    }
}

// ---------------- the mega kernel ----------------
struct MArgs {
    const float *enc, *encW, *dec, *sv;
    const int* len;
    const float *pw1, *pb1, *pw2, *pb2, *wdec_, *bdec;
    const float *ga_ih, *ga_bih, *ga_bhh, *wattn, *battn;
    const float *wsc, *bsc, *g1_ih, *g1_bih, *g1_bhh;
    const float *g2_ih, *g2_bih, *g2_bhh, *wout_, *bout;
    float* out;
};

__global__ __launch_bounds__(NTHR) void mega(MArgs a)
{
    extern __shared__ float sm[];
    const int tid  = threadIdx.x;
    const int half = tid >> 8;
    const int htid = tid & 255;
    float* smh = sm + half * 12800;
    const int BIGJ = 1 << 30;
    float pf = 0.f;

    // S1: pre1 partials (M=512,K=80,KC=32,jt=4,ks=3)  + prefetch
    gemm_stage<32>(XDirect{a.dec, 80}, a.pw1, BIGJ, a.pw1, 80, BIGJ, 0,
                   512, 80, 4, 3, g_P + OFF_P1, 512, smh, half, htid);
    pf += prefetch_batch(a.enc, a.encW, a.len, 2, smh, half, htid);
    gbar(1);

    // S2: pre2 partials (M=256,K=512,KC=64,jt=2,ks=8)  + prefetch
    gemm_stage<64>(XPre1Red{g_P + OFF_P1, a.pb1}, a.pw2, BIGJ, a.pw2, 512, BIGJ, 0,
                   256, 512, 2, 8, g_P + OFF_P2, 256, smh, half, htid);
    pf += prefetch_batch(a.enc, a.encW, a.len, 2, smh, half, htid);
    gbar(2);

    // S4: gruA input GEMM (M=1536,K=384,KC=32,jt=12,ks=12)  + prefetch
    gemm_stage<32>(XPre2Red{g_P + OFF_P2, a.pb2, a.sv}, a.ga_ih, BIGJ, a.ga_ih, 896,
                   256, 512, 1536, 384, 12, 12, g_P + OFF_A, 1536, smh, half, htid);
    pf += prefetch_batch(a.enc, a.encW, a.len, 2, smh, half, htid);
    gbar(3);

    // S6: wdec partials (M=512,K=512,KC=64,jt=4,ks=8); X = gruA reduce on the fly.
    {
        XGruARed xga{g_P + OFF_A, a.ga_bih, a.ga_bhh};
        for (int idx = blockIdx.x * NTHR + tid; idx < 64 * 128; idx += NBLK * NTHR) {
            int n = idx >> 7, c = (idx & 127) << 2;
            *reinterpret_cast<float4*>(g_oatt + n * 512 + c) = xga.load4(n, c);
        }
        gemm_stage<64>(xga, a.wdec_, BIGJ, a.wdec_, 512, BIGJ, 0,
                       512, 512, 4, 8, g_P + OFF_W, 512, smh, half, htid);
    }
    pf += prefetch_batch(a.enc, a.encW, a.len, 2, smh, half, htid);
    gbar(4);

    // S8: attention (phase A scores, phase B column stream), work-stealing
    attention_phase(a.encW, a.enc, a.wattn, a.battn, a.bdec, a.len, smh, half, htid);
    gbar(5);

    // S10: fused wsc|g1 GEMM (M=2048,K=1152,KC=64,jt=16,ks=18); X = out_dec on the fly.
    {
        XOdecRed xod{g_part, g_wpart, g_oatt, a.sv};
        for (int idx = blockIdx.x * NTHR + tid; idx < 64 * 128; idx += NBLK * NTHR) {
            int n = idx >> 7, c = (idx & 127) << 2;
            *reinterpret_cast<float4*>(a.out + 10240 + (size_t)n * 512 + c) = xod.load4(n, c);
        }
        gemm_stage<64>(xod, a.wsc, 512, a.g1_ih, 1152, BIGJ, 0,
                       2048, 1152, 16, 18, g_P + OFF_G, 2048, smh, half, htid);
    }
    gbar(6);

    // S11: residual = sc + gru1 -> res1
    for (int idx = blockIdx.x * NTHR + tid; idx < 64 * 512; idx += NBLK * NTHR) {
        int n = idx >> 9, j = idx & 511;
        float sc = a.bsc[j], gr = a.g1_bih[j], gz = a.g1_bih[512 + j], gn = a.g1_bih[1024 + j];
        for (int s = 0; s < 18; s++) {
            const float* pp = g_P + OFF_G + (size_t)s * 131072 + (size_t)n * 2048;
            sc += pp[j]; gr += pp[512 + j]; gz += pp[1024 + j]; gn += pp[1536 + j];
        }
        g_res1[idx] = sc + gru_out(gr, gz, gn, a.g1_bhh[j], a.g1_bhh[512 + j], a.g1_bhh[1024 + j]);
    }
    gbar(7);

    // S12: g2 GEMM (M=1536,K=512,KC=32,jt=12,ks=16)
    gemm_stage<32>(XDirect{g_res1, 512}, a.g2_ih, BIGJ, a.g2_ih, 512, BIGJ, 0,
                   1536, 512, 12, 16, g_P + OFF_2, 1536, smh, half, htid);
    gbar(8);

    // S14: wout GEMM (M=160,K=512,KC=32,jt=2,ks=16); X = res1 + gru2 reduce on the fly
    gemm_stage<32>(XGru2Red{g_P + OFF_2, a.g2_bih, a.g2_bhh, g_res1},
                   a.wout_, BIGJ, a.wout_, 512, BIGJ, 0,
                   160, 512, 2, 16, g_P + OFF_O, 160, smh, half, htid);
    gbar(9);

    // S15: wout reduce -> d_out[0:10240]
    for (int idx = blockIdx.x * NTHR + tid; idx < 64 * 160; idx += NBLK * NTHR) {
        int n = idx / 160, j = idx - n * 160;
        float s = a.bout[j];
#pragma unroll
        for (int sp = 0; sp < 16; sp++) s += g_P[OFF_O + sp * 10240 + n * 160 + j];
        a.out[idx] = s;
    }

    // keep prefetch loads observable (never true on real data)
    if (__float_as_uint(pf) == 0x7F800001u) g_dummy[0] = pf;
}

// ---------------- host orchestration ----------------
extern "C" void kernel_launch(void* const* d_in, const int* in_sizes, int n_in,
                              void* d_out, int out_size)
{
    (void)n_in; (void)out_size;
    bool dictord = (in_sizes[4] == 64);
    int b = dictord ? 5 : 4;

    MArgs a;
    a.enc   = (const float*)d_in[0];
    a.encW  = (const float*)d_in[1];
    a.dec   = (const float*)d_in[2];
    a.sv    = (const float*)d_in[3];
    a.len   = (const int*)(dictord ? d_in[4] : d_in[28]);
    a.pw1   = (const float*)d_in[b + 0];
    a.pb1   = (const float*)d_in[b + 1];
    a.pw2   = (const float*)d_in[b + 2];
    a.pb2   = (const float*)d_in[b + 3];
    a.wdec_ = (const float*)d_in[b + 4];
    a.bdec  = (const float*)d_in[b + 5];
    a.ga_ih = (const float*)d_in[b + 6];
    a.ga_bih= (const float*)d_in[b + 8];
    a.ga_bhh= (const float*)d_in[b + 9];
    a.wattn = (const float*)d_in[b + 10];
    a.battn = (const float*)d_in[b + 11];
    a.wsc   = (const float*)d_in[b + 12];
    a.bsc   = (const float*)d_in[b + 13];
    a.g1_ih = (const float*)d_in[b + 14];
    a.g1_bih= (const float*)d_in[b + 16];
    a.g1_bhh= (const float*)d_in[b + 17];
    a.g2_ih = (const float*)d_in[b + 18];
    a.g2_bih= (const float*)d_in[b + 20];
    a.g2_bhh= (const float*)d_in[b + 21];
    a.wout_ = (const float*)d_in[b + 22];
    a.bout  = (const float*)d_in[b + 23];
    a.out   = (float*)d_out;

    static bool attr_set = false;
    if (!attr_set) {
        cudaFuncSetAttribute(mega, cudaFuncAttributeMaxDynamicSharedMemorySize, 102400);
        attr_set = true;
    }

    void* sync;
    cudaGetSymbolAddress(&sync, g_sync);
    cudaMemsetAsync(sync, 0, (64 + 148 * 32) * sizeof(unsigned));

    mega<<<NBLK, NTHR, 102400>>>(a);
}

// round 6
// speedup vs baseline: 1.0187x; 1.0187x over previous
#include <cuda_runtime.h>
#include <cstdint>

#define NBLK 148
#define NTHR 512

// ---------------- static device scratch ----------------
__device__ __align__(16) float g_P[5767168];
__device__ __align__(16) float g_oatt[64 * 512];
__device__ __align__(16) float g_res1[64 * 512];
__device__ __align__(16) float g_part[64 * 8 * 512];
__device__ __align__(16) float g_wpart[512];
// [0]=attention steal, flags at 64 + bid*32 (one 128B line per CTA)
__device__ unsigned g_sync[64 + 148 * 32];

// partial-region offsets (floats)
#define OFF_P1 0        // pre1:  ns=3,  ldp=512
#define OFF_P2 98304    // pre2:  ns=8,  ldp=256
#define OFF_A  229376   // gruA:  ns=12, ldp=1536
#define OFF_W  1409024  // wdec:  ns=8,  ldp=512
#define OFF_G  1671168  // wsc|g1:ns=18, ldp=2048
#define OFF_2  4030464  // g2:    ns=16, ldp=1536
#define OFF_O  5603328  // wout:  ns=16, ldp=160

__device__ __forceinline__ float tanh_fast(float x) {
    float y; asm("tanh.approx.f32 %0, %1;" : "=f"(y) : "f"(x)); return y;
}
__device__ __forceinline__ float gru_out(float gr, float gz, float gn,
                                         float br, float bz, float bn) {
    float r  = 1.f / (1.f + __expf(-(gr + br)));
    float z  = 1.f / (1.f + __expf(-(gz + bz)));
    float nn = tanhf(gn + r * bn);
    return (1.f - z) * nn;
}
__device__ __forceinline__ void add4(float4& a, const float4 b) {
    a.x += b.x; a.y += b.y; a.z += b.z; a.w += b.w;
}
__device__ __forceinline__ void bar_half(int half) {
    asm volatile("bar.sync %0, 256;" :: "r"(half + 1) : "memory");
}

// flag-array grid barrier: per-CTA release-store, distributed acquire-poll.
__device__ __forceinline__ void gbar(unsigned ep) {
    __syncthreads();
    if (threadIdx.x == 0) {
        asm volatile("st.release.gpu.global.u32 [%0], %1;"
                     :: "l"(g_sync + 64 + blockIdx.x * 32), "r"(ep) : "memory");
    }
    if (threadIdx.x < 148) {
        const unsigned* p = g_sync + 64 + threadIdx.x * 32;
        unsigned v;
        do {
            asm volatile("ld.acquire.gpu.global.u32 %0, [%1];"
                         : "=r"(v) : "l"(p) : "memory");
        } while (v < ep);
    }
    __syncthreads();
}

// ---------------- X functors ----------------
struct XDirect {
    const float* X; int ldx;
    __device__ __forceinline__ float4 load4(int n, int k) const {
        return *reinterpret_cast<const float4*>(X + (size_t)n * ldx + k);
    }
    __device__ __forceinline__ float load1(int n, int k) const {
        return X[(size_t)n * ldx + k];
    }
};
struct XPre1Red {
    const float* P1; const float* pb1;
    __device__ __forceinline__ float4 load4(int n, int k) const {
        float4 s = *reinterpret_cast<const float4*>(pb1 + k);
#pragma unroll
        for (int sp = 0; sp < 3; sp++)
            add4(s, *reinterpret_cast<const float4*>(P1 + sp * 32768 + n * 512 + k));
        s.x = fmaxf(s.x, 0.f); s.y = fmaxf(s.y, 0.f);
        s.z = fmaxf(s.z, 0.f); s.w = fmaxf(s.w, 0.f);
        return s;
    }
    __device__ __forceinline__ float load1(int n, int k) const {
        float s = pb1[k];
        for (int sp = 0; sp < 3; sp++) s += P1[sp * 32768 + n * 512 + k];
        return fmaxf(s, 0.f);
    }
};
struct XPre2Red {
    const float* P2; const float* pb2; const float* sv;
    __device__ __forceinline__ float4 load4(int n, int k) const {
        if (k < 256) {
            float4 s = *reinterpret_cast<const float4*>(pb2 + k);
#pragma unroll
            for (int sp = 0; sp < 8; sp++)
                add4(s, *reinterpret_cast<const float4*>(P2 + sp * 16384 + n * 256 + k));
            s.x = fmaxf(s.x, 0.f); s.y = fmaxf(s.y, 0.f);
            s.z = fmaxf(s.z, 0.f); s.w = fmaxf(s.w, 0.f);
            return s;
        }
        return *reinterpret_cast<const float4*>(sv + n * 128 + (k - 256));
    }
    __device__ __forceinline__ float load1(int n, int k) const {
        if (k < 256) {
            float s = pb2[k];
            for (int sp = 0; sp < 8; sp++) s += P2[sp * 16384 + n * 256 + k];
            return fmaxf(s, 0.f);
        }
        return sv[n * 128 + (k - 256)];
    }
};
struct XGruARed {
    const float* P; const float* bih; const float* bhh;
    __device__ __forceinline__ float4 load4(int n, int k) const {
        const float* b = P + (size_t)n * 1536 + k;
        float4 r = *reinterpret_cast<const float4*>(bih + k);
        float4 z = *reinterpret_cast<const float4*>(bih + 512 + k);
        float4 m = *reinterpret_cast<const float4*>(bih + 1024 + k);
#pragma unroll
        for (int sp = 0; sp < 12; sp++) {
            const float* q = b + (size_t)sp * 98304;
            add4(r, *reinterpret_cast<const float4*>(q));
            add4(z, *reinterpret_cast<const float4*>(q + 512));
            add4(m, *reinterpret_cast<const float4*>(q + 1024));
        }
        float4 br = *reinterpret_cast<const float4*>(bhh + k);
        float4 bz = *reinterpret_cast<const float4*>(bhh + 512 + k);
        float4 bn = *reinterpret_cast<const float4*>(bhh + 1024 + k);
        float4 o;
        o.x = gru_out(r.x, z.x, m.x, br.x, bz.x, bn.x);
        o.y = gru_out(r.y, z.y, m.y, br.y, bz.y, bn.y);
        o.z = gru_out(r.z, z.z, m.z, br.z, bz.z, bn.z);
        o.w = gru_out(r.w, z.w, m.w, br.w, bz.w, bn.w);
        return o;
    }
    __device__ __forceinline__ float load1(int n, int k) const {
        float gr = bih[k], gz = bih[512 + k], gn = bih[1024 + k];
        for (int sp = 0; sp < 12; sp++) {
            const float* q = P + (size_t)sp * 98304 + (size_t)n * 1536 + k;
            gr += q[0]; gz += q[512]; gn += q[1024];
        }
        return gru_out(gr, gz, gn, bhh[k], bhh[512 + k], bhh[1024 + k]);
    }
};
struct XOdecRed {
    const float* part; const float* wpart; const float* oatt; const float* sv;
    __device__ __forceinline__ float4 load4(int n, int k) const {
        if (k < 512) {
            float4 s = make_float4(0.f, 0.f, 0.f, 0.f);
            float w = 0.f;
#pragma unroll
            for (int sp = 0; sp < 8; sp++) {
                add4(s, *reinterpret_cast<const float4*>(part + (size_t)(n * 8 + sp) * 512 + k));
                w += wpart[n * 8 + sp];
            }
            float inv = 1.f / fmaxf(w, 1e-12f);
            s.x *= inv; s.y *= inv; s.z *= inv; s.w *= inv;
            return s;
        }
        if (k < 1024) return *reinterpret_cast<const float4*>(oatt + n * 512 + (k - 512));
        return *reinterpret_cast<const float4*>(sv + n * 128 + (k - 1024));
    }
    __device__ __forceinline__ float load1(int n, int k) const {
        if (k < 512) {
            float s = 0.f, w = 0.f;
            for (int sp = 0; sp < 8; sp++) {
                s += part[(size_t)(n * 8 + sp) * 512 + k];
                w += wpart[n * 8 + sp];
            }
            return s / fmaxf(w, 1e-12f);
        }
        if (k < 1024) return oatt[n * 512 + (k - 512)];
        return sv[n * 128 + (k - 1024)];
    }
};
struct XGru2Red {
    const float* P; const float* bih; const float* bhh; const float* res1;
    __device__ __forceinline__ float4 load4(int n, int k) const {
        const float* b = P + (size_t)n * 1536 + k;
        float4 r = *reinterpret_cast<const float4*>(bih + k);
        float4 z = *reinterpret_cast<const float4*>(bih + 512 + k);
        float4 m = *reinterpret_cast<const float4*>(bih + 1024 + k);
#pragma unroll
        for (int sp = 0; sp < 16; sp++) {
            const float* q = b + (size_t)sp * 98304;
            add4(r, *reinterpret_cast<const float4*>(q));
            add4(z, *reinterpret_cast<const float4*>(q + 512));
            add4(m, *reinterpret_cast<const float4*>(q + 1024));
        }
        float4 br = *reinterpret_cast<const float4*>(bhh + k);
        float4 bz = *reinterpret_cast<const float4*>(bhh + 512 + k);
        float4 bn = *reinterpret_cast<const float4*>(bhh + 1024 + k);
        float4 rv = *reinterpret_cast<const float4*>(res1 + n * 512 + k);
        float4 o;
        o.x = gru_out(r.x, z.x, m.x, br.x, bz.x, bn.x) + rv.x;
        o.y = gru_out(r.y, z.y, m.y, br.y, bz.y, bn.y) + rv.y;
        o.z = gru_out(r.z, z.z, m.z, br.z, bz.z, bn.z) + rv.z;
        o.w = gru_out(r.w, z.w, m.w, br.w, bz.w, bn.w) + rv.w;
        return o;
    }
    __device__ __forceinline__ float load1(int n, int k) const {
        float gr = bih[k], gz = bih[512 + k], gn = bih[1024 + k];
        for (int sp = 0; sp < 16; sp++) {
            const float* q = P + (size_t)sp * 98304 + (size_t)n * 1536 + k;
            gr += q[0]; gz += q[512]; gn += q[1024];
        }
        return gru_out(gr, gz, gn, bhh[k], bhh[512 + k], bhh[1024 + k]) + res1[n * 512 + k];
    }
};

// ---------------- dual-worker k-split GEMM stage ----------------
template <int KC, class XF>
__device__ __forceinline__ void gemm_stage(
    const XF xf,
    const float* __restrict__ W1, int m1, const float* __restrict__ W2, int ldw,
    int kjump_at, int kjump_ofs,
    int M, int K, int jt_n, int ks_n,
    float* __restrict__ P, int ldp, float* __restrict__ smh, int half, int htid)
{
    constexpr int K4 = KC / 4;
    constexpr int SH = (KC == 64) ? 4 : 3;
    float* xs = smh;            // [KC][68]
    float* ws = smh + KC * 68;  // [KC][132]
    const int items = jt_n * ks_n;

    for (int it = blockIdx.x * 2 + half; it < items; it += 2 * NBLK) {
        const int ksp = it / jt_n;
        const int jt  = it - ksp * jt_n;
        const int j0  = jt << 7;
        const int k0  = ksp * KC;
        for (int idx = htid; idx < K4 * 64; idx += 256) {
            int k4 = idx & (K4 - 1), n = idx >> SH;
            int kk = k0 + (k4 << 2);
            float4 v = make_float4(0.f, 0.f, 0.f, 0.f);
            if (kk + 3 < K) v = xf.load4(n, kk);
            else {
                if (kk + 0 < K) v.x = xf.load1(n, kk + 0);
                if (kk + 1 < K) v.y = xf.load1(n, kk + 1);
                if (kk + 2 < K) v.z = xf.load1(n, kk + 2);
                if (kk + 3 < K) v.w = xf.load1(n, kk + 3);
            }
            float* d = xs + (k4 << 2) * 68 + n;
            d[0] = v.x; d[68] = v.y; d[136] = v.z; d[204] = v.w;
        }
        const int wofs = k0 + (k0 >= kjump_at ? kjump_ofs : 0);
        for (int idx = htid; idx < K4 * 128; idx += 256) {
            int k4 = idx & (K4 - 1), j = idx >> SH;
            int jr = j0 + j;
            float4 v = make_float4(0.f, 0.f, 0.f, 0.f);
            if (jr < M) {
                const float* Wr = (jr < m1) ? (W1 + (size_t)jr * ldw)
                                            : (W2 + (size_t)(jr - m1) * ldw);
                int kk = k0 + (k4 << 2);
                if (kk + 3 < K) v = *reinterpret_cast<const float4*>(Wr + wofs + (k4 << 2));
                else {
                    if (kk + 0 < K) v.x = Wr[wofs + (k4 << 2) + 0];
                    if (kk + 1 < K) v.y = Wr[wofs + (k4 << 2) + 1];
                    if (kk + 2 < K) v.z = Wr[wofs + (k4 << 2) + 2];
                    if (kk + 3 < K) v.w = Wr[wofs + (k4 << 2) + 3];
                }
            }
            float* d = ws + (k4 << 2) * 132 + j;
            d[0] = v.x; d[132] = v.y; d[264] = v.z; d[396] = v.w;
        }
        bar_half(half);

        const int tj = htid & 31, tn = htid >> 5;
        float acc[4][8];
#pragma unroll
        for (int a = 0; a < 4; a++)
#pragma unroll
            for (int b = 0; b < 8; b++) acc[a][b] = 0.f;

#pragma unroll 8
        for (int k = 0; k < KC; k++) {
            float4 wv = *reinterpret_cast<const float4*>(ws + k * 132 + tj * 4);
            float4 xa = *reinterpret_cast<const float4*>(xs + k * 68 + tn * 8);
            float4 xb = *reinterpret_cast<const float4*>(xs + k * 68 + tn * 8 + 4);
            float xv[8] = {xa.x, xa.y, xa.z, xa.w, xb.x, xb.y, xb.z, xb.w};
            float wr[4] = {wv.x, wv.y, wv.z, wv.w};
#pragma unroll
            for (int jj = 0; jj < 4; jj++)
#pragma unroll
                for (int i = 0; i < 8; i++) acc[jj][i] += wr[jj] * xv[i];
        }

        if (j0 + tj * 4 < M) {
            float* base = P + (size_t)ksp * (64 * ldp) + j0 + tj * 4;
#pragma unroll
            for (int i = 0; i < 8; i++) {
                int n = tn * 8 + i;
                *reinterpret_cast<float4*>(base + (size_t)n * ldp) =
                    make_float4(acc[0][i], acc[1][i], acc[2][i], acc[3][i]);
            }
        }
        bar_half(half);
    }
}

// ---------------- attention: phase A (8-row batched scores) + phase B (column stream) ----------------
__device__ void attention_phase(const float* __restrict__ encW, const float* __restrict__ enc,
                                const float* __restrict__ wattn, const float* __restrict__ battn,
                                const float* __restrict__ bdec, const int* __restrict__ len,
                                float* __restrict__ smh, int half, int htid)
{
    float* wv_s = smh;           // 512
    float* aw_s = smh + 512;     // 512
    float* we_s = smh + 1024;    // 128
    float* wred = smh + 1152;    // 8
    int*   ip   = (int*)(smh + 1160);
    float* cacc = smh + 1168;    // 256 float4
    const float* PW = g_P + OFF_W;
    const int lane = htid & 31, warp = htid >> 5;
    const float bat = battn[0];

    for (int c = htid; c < 512; c += 256) wv_s[c] = wattn[c];

    for (;;) {
        if (htid == 0) *ip = (int)atomicAdd(&g_sync[0], 1u);
        bar_half(half);
        const int item = *ip;
        bar_half(half);
        if (item >= 512) break;
        const int n = item >> 3, t0 = (item & 7) << 7;
        const int tc = min(128, len[n] - t0);
        if (tc <= 0) {
            for (int c = htid; c < 512; c += 256) g_part[(size_t)item * 512 + c] = 0.f;
            if (htid == 0) g_wpart[item] = 0.f;
            continue;
        }
        // build attW[n] from wdec partials (+ bdec)
        for (int c4 = htid; c4 < 128; c4 += 256) {
            int c = c4 << 2;
            float4 s = *reinterpret_cast<const float4*>(bdec + c);
#pragma unroll
            for (int sp = 0; sp < 8; sp++)
                add4(s, *reinterpret_cast<const float4*>(PW + sp * 32768 + n * 512 + c));
            *reinterpret_cast<float4*>(aw_s + c) = s;
        }
        bar_half(half);

        // phase A: scores, 8 rows per warp-superiteration (32 independent f4 loads,
        // 8 independent FMA chains, pipelined shuffles)
        float wsum = 0.f;
        const size_t rb = (size_t)(n * 1024 + t0) * 512;
        for (int tt0 = warp * 8; tt0 < tc; tt0 += 64) {
            float s[8];
            // preload aw/wv slices once per superiteration
            float4 awr[4], wvr[4];
#pragma unroll
            for (int q = 0; q < 4; q++) {
                int c = lane * 4 + q * 128;
                awr[q] = *reinterpret_cast<const float4*>(aw_s + c);
                wvr[q] = *reinterpret_cast<const float4*>(wv_s + c);
            }
#pragma unroll
            for (int i = 0; i < 8; i++) {
                int r = tt0 + i;
                float si = 0.f;
                if (r < tc) {
                    const float* rp = encW + rb + (size_t)r * 512;
#pragma unroll
                    for (int q = 0; q < 4; q++) {
                        int c = lane * 4 + q * 128;
                        float4 v = *reinterpret_cast<const float4*>(rp + c);
                        si += tanh_fast(v.x + awr[q].x) * wvr[q].x
                            + tanh_fast(v.y + awr[q].y) * wvr[q].y
                            + tanh_fast(v.z + awr[q].z) * wvr[q].z
                            + tanh_fast(v.w + awr[q].w) * wvr[q].w;
                    }
                }
                s[i] = si;
            }
            // 8 independent butterfly reductions (pipelined shuffles)
#pragma unroll
            for (int o = 16; o > 0; o >>= 1) {
#pragma unroll
                for (int i = 0; i < 8; i++)
                    s[i] += __shfl_xor_sync(0xffffffffu, s[i], o);
            }
            if (lane == 0) {
#pragma unroll
                for (int i = 0; i < 8; i++) {
                    int r = tt0 + i;
                    if (r < tc) {
                        float w = __expf(s[i] + bat);
                        we_s[r] = w;
                        wsum += w;
                    }
                }
            }
        }
        if (lane == 0) wred[warp] = wsum;
        bar_half(half);

        // phase B: weighted column sums (streams enc; no shuffles, deep MLP)
        {
            const int col = (htid & 127) << 2;
            const int rh = htid >> 7;
            const float* base = enc + rb + col;
            float4 acc = make_float4(0.f, 0.f, 0.f, 0.f);
            int r = rh;
            for (; r + 14 < tc; r += 16) {
                float w0 = we_s[r],      w1 = we_s[r + 2],  w2 = we_s[r + 4],  w3 = we_s[r + 6];
                float w4 = we_s[r + 8],  w5 = we_s[r + 10], w6 = we_s[r + 12], w7 = we_s[r + 14];
                float4 v0 = *reinterpret_cast<const float4*>(base + (size_t)(r +  0) * 512);
                float4 v1 = *reinterpret_cast<const float4*>(base + (size_t)(r +  2) * 512);
                float4 v2 = *reinterpret_cast<const float4*>(base + (size_t)(r +  4) * 512);
                float4 v3 = *reinterpret_cast<const float4*>(base + (size_t)(r +  6) * 512);
                float4 v4 = *reinterpret_cast<const float4*>(base + (size_t)(r +  8) * 512);
                float4 v5 = *reinterpret_cast<const float4*>(base + (size_t)(r + 10) * 512);
                float4 v6 = *reinterpret_cast<const float4*>(base + (size_t)(r + 12) * 512);
                float4 v7 = *reinterpret_cast<const float4*>(base + (size_t)(r + 14) * 512);
                acc.x += w0*v0.x + w1*v1.x + w2*v2.x + w3*v3.x + w4*v4.x + w5*v5.x + w6*v6.x + w7*v7.x;
                acc.y += w0*v0.y + w1*v1.y + w2*v2.y + w3*v3.y + w4*v4.y + w5*v5.y + w6*v6.y + w7*v7.y;
                acc.z += w0*v0.z + w1*v1.z + w2*v2.z + w3*v3.z + w4*v4.z + w5*v5.z + w6*v6.z + w7*v7.z;
                acc.w += w0*v0.w + w1*v1.w + w2*v2.w + w3*v3.w + w4*v4.w + w5*v5.w + w6*v6.w + w7*v7.w;
            }
            for (; r < tc; r += 2) {
                float w = we_s[r];
                float4 v = *reinterpret_cast<const float4*>(base + (size_t)r * 512);
                acc.x += w * v.x; acc.y += w * v.y; acc.z += w * v.z; acc.w += w * v.w;
            }
            *reinterpret_cast<float4*>(cacc + htid * 4) = acc;
        }
        bar_half(half);
        if (htid < 128) {
            float4 x = *reinterpret_cast<const float4*>(cacc + htid * 4);
            float4 y = *reinterpret_cast<const float4*>(cacc + (htid + 128) * 4);
            add4(x, y);
            *reinterpret_cast<float4*>(g_part + (size_t)item * 512 + htid * 4) = x;
        }
        if (htid == 0) {
            float s = 0.f;
#pragma unroll
            for (int w = 0; w < 8; w++) s += wred[w];
            g_wpart[item] = s;
        }
        bar_half(half);
    }
}

// ---------------- the mega kernel ----------------
struct MArgs {
    const float *enc, *encW, *dec, *sv;
    const int* len;
    const float *pw1, *pb1, *pw2, *pb2, *wdec_, *bdec;
    const float *ga_ih, *ga_bih, *ga_bhh, *wattn, *battn;
    const float *wsc, *bsc, *g1_ih, *g1_bih, *g1_bhh;
    const float *g2_ih, *g2_bih, *g2_bhh, *wout_, *bout;
    float* out;
};

__global__ __launch_bounds__(NTHR) void mega(MArgs a)
{
    extern __shared__ float sm[];
    const int tid  = threadIdx.x;
    const int half = tid >> 8;
    const int htid = tid & 255;
    float* smh = sm + half * 12800;
    const int BIGJ = 1 << 30;

    // S1: pre1 partials (M=512,K=80,KC=32,jt=4,ks=3)
    gemm_stage<32>(XDirect{a.dec, 80}, a.pw1, BIGJ, a.pw1, 80, BIGJ, 0,
                   512, 80, 4, 3, g_P + OFF_P1, 512, smh, half, htid);
    gbar(1);

    // S2: pre2 partials (M=256,K=512,KC=64,jt=2,ks=8); X = relu(pre1-reduce)
    gemm_stage<64>(XPre1Red{g_P + OFF_P1, a.pb1}, a.pw2, BIGJ, a.pw2, 512, BIGJ, 0,
                   256, 512, 2, 8, g_P + OFF_P2, 256, smh, half, htid);
    gbar(2);

    // S4: gruA input GEMM (M=1536,K=384,KC=32,jt=12,ks=12), W col jump at 256 (+512)
    gemm_stage<32>(XPre2Red{g_P + OFF_P2, a.pb2, a.sv}, a.ga_ih, BIGJ, a.ga_ih, 896,
                   256, 512, 1536, 384, 12, 12, g_P + OFF_A, 1536, smh, half, htid);
    gbar(3);

    // S6: wdec partials (M=512,K=512,KC=64,jt=4,ks=8); X = gruA reduce on the fly.
    {
        XGruARed xga{g_P + OFF_A, a.ga_bih, a.ga_bhh};
        for (int idx = blockIdx.x * NTHR + tid; idx < 64 * 128; idx += NBLK * NTHR) {
            int n = idx >> 7, c = (idx & 127) << 2;
            *reinterpret_cast<float4*>(g_oatt + n * 512 + c) = xga.load4(n, c);
        }
        gemm_stage<64>(xga, a.wdec_, BIGJ, a.wdec_, 512, BIGJ, 0,
                       512, 512, 4, 8, g_P + OFF_W, 512, smh, half, htid);
    }
    gbar(4);

    // S8: attention (phase A scores batched, phase B column stream), work-stealing
    attention_phase(a.encW, a.enc, a.wattn, a.battn, a.bdec, a.len, smh, half, htid);
    gbar(5);

    // S10: fused wsc|g1 GEMM (M=2048,K=1152,KC=64,jt=16,ks=18); X = out_dec on the fly.
    {
        XOdecRed xod{g_part, g_wpart, g_oatt, a.sv};
        for (int idx = blockIdx.x * NTHR + tid; idx < 64 * 128; idx += NBLK * NTHR) {
            int n = idx >> 7, c = (idx & 127) << 2;
            *reinterpret_cast<float4*>(a.out + 10240 + (size_t)n * 512 + c) = xod.load4(n, c);
        }
        gemm_stage<64>(xod, a.wsc, 512, a.g1_ih, 1152, BIGJ, 0,
                       2048, 1152, 16, 18, g_P + OFF_G, 2048, smh, half, htid);
    }
    gbar(6);

    // S11: residual = sc + gru1 -> res1
    for (int idx = blockIdx.x * NTHR + tid; idx < 64 * 512; idx += NBLK * NTHR) {
        int n = idx >> 9, j = idx & 511;
        float sc = a.bsc[j], gr = a.g1_bih[j], gz = a.g1_bih[512 + j], gn = a.g1_bih[1024 + j];
        for (int s = 0; s < 18; s++) {
            const float* pp = g_P + OFF_G + (size_t)s * 131072 + (size_t)n * 2048;
            sc += pp[j]; gr += pp[512 + j]; gz += pp[1024 + j]; gn += pp[1536 + j];
        }
        g_res1[idx] = sc + gru_out(gr, gz, gn, a.g1_bhh[j], a.g1_bhh[512 + j], a.g1_bhh[1024 + j]);
    }
    gbar(7);

    // S12: g2 GEMM (M=1536,K=512,KC=32,jt=12,ks=16)
    gemm_stage<32>(XDirect{g_res1, 512}, a.g2_ih, BIGJ, a.g2_ih, 512, BIGJ, 0,
                   1536, 512, 12, 16, g_P + OFF_2, 1536, smh, half, htid);
    gbar(8);

    // S14: wout GEMM (M=160,K=512,KC=32,jt=2,ks=16); X = res1 + gru2 reduce on the fly
    gemm_stage<32>(XGru2Red{g_P + OFF_2, a.g2_bih, a.g2_bhh, g_res1},
                   a.wout_, BIGJ, a.wout_, 512, BIGJ, 0,
                   160, 512, 2, 16, g_P + OFF_O, 160, smh, half, htid);
    gbar(9);

    // S15: wout reduce -> d_out[0:10240]
    for (int idx = blockIdx.x * NTHR + tid; idx < 64 * 160; idx += NBLK * NTHR) {
        int n = idx / 160, j = idx - n * 160;
        float s = a.bout[j];
#pragma unroll
        for (int sp = 0; sp < 16; sp++) s += g_P[OFF_O + sp * 10240 + n * 160 + j];
        a.out[idx] = s;
    }
}

// ---------------- host orchestration ----------------
extern "C" void kernel_launch(void* const* d_in, const int* in_sizes, int n_in,
                              void* d_out, int out_size)
{
    (void)n_in; (void)out_size;
    bool dictord = (in_sizes[4] == 64);
    int b = dictord ? 5 : 4;

    MArgs a;
    a.enc   = (const float*)d_in[0];
    a.encW  = (const float*)d_in[1];
    a.dec   = (const float*)d_in[2];
    a.sv    = (const float*)d_in[3];
    a.len   = (const int*)(dictord ? d_in[4] : d_in[28]);
    a.pw1   = (const float*)d_in[b + 0];
    a.pb1   = (const float*)d_in[b + 1];
    a.pw2   = (const float*)d_in[b + 2];
    a.pb2   = (const float*)d_in[b + 3];
    a.wdec_ = (const float*)d_in[b + 4];
    a.bdec  = (const float*)d_in[b + 5];
    a.ga_ih = (const float*)d_in[b + 6];
    a.ga_bih= (const float*)d_in[b + 8];
    a.ga_bhh= (const float*)d_in[b + 9];
    a.wattn = (const float*)d_in[b + 10];
    a.battn = (const float*)d_in[b + 11];
    a.wsc   = (const float*)d_in[b + 12];
    a.bsc   = (const float*)d_in[b + 13];
    a.g1_ih = (const float*)d_in[b + 14];
    a.g1_bih= (const float*)d_in[b + 16];
    a.g1_bhh= (const float*)d_in[b + 17];
    a.g2_ih = (const float*)d_in[b + 18];
    a.g2_bih= (const float*)d_in[b + 20];
    a.g2_bhh= (const float*)d_in[b + 21];
    a.wout_ = (const float*)d_in[b + 22];
    a.bout  = (const float*)d_in[b + 23];
    a.out   = (float*)d_out;

    static bool attr_set = false;
    if (!attr_set) {
        cudaFuncSetAttribute(mega, cudaFuncAttributeMaxDynamicSharedMemorySize, 102400);
        attr_set = true;
    }

    void* sync;
    cudaGetSymbolAddress(&sync, g_sync);
    cudaMemsetAsync(sync, 0, (64 + 148 * 32) * sizeof(unsigned));

    mega<<<NBLK, NTHR, 102400>>>(a);
}